// round 3
// baseline (speedup 1.0000x reference)
#include <cuda_runtime.h>
#include <math.h>

#define BB  4
#define TT  2048
#define DD  1024
#define HH  16
#define HDD 64
#define BHH (BB*HH)

// QKV scratch in head-split layout: [3][B*H][T][HD]
__device__ float g_qkv[3ULL * BHH * TT * HDD];

// ---------------------------------------------------------------------------
// QKV projection: C = X @ W + b, written head-split. z selects Q/K/V.
// 128x128 output tile, BK=8, 256 threads, 8x8 per thread.
// ---------------------------------------------------------------------------
__global__ void __launch_bounds__(256) qkv_gemm_kernel(
    const float* __restrict__ X,
    const float* __restrict__ Wq, const float* __restrict__ bq,
    const float* __restrict__ Wk, const float* __restrict__ bk,
    const float* __restrict__ Wv, const float* __restrict__ bv)
{
    const int z = blockIdx.z;
    const float* Wm   = (z == 0) ? Wq : (z == 1) ? Wk : Wv;
    const float* bias = (z == 0) ? bq : (z == 1) ? bk : bv;

    __shared__ float As[8][128];   // As[k][m]
    __shared__ float Bs[8][128];   // Bs[k][n]

    const int tid = threadIdx.x;
    const int bn = blockIdx.x;     // N tile (8 tiles)
    const int bm = blockIdx.y;     // M tile (64 tiles)
    const int tr = tid >> 4;       // 0..15
    const int tc = tid & 15;       // 0..15

    const int arow = tid >> 1;          // 0..127
    const int acol = (tid & 1) * 4;     // 0 or 4
    const int brow = tid >> 5;          // 0..7
    const int bcol = (tid & 31) * 4;    // 0..124

    const float* Aptr = X  + (size_t)(bm * 128 + arow) * DD + acol;
    const float* Bptr = Wm + (size_t)brow * DD + bn * 128 + bcol;

    float acc[8][8] = {};

    for (int kk = 0; kk < DD; kk += 8) {
        float4 av  = *(const float4*)(Aptr + kk);
        float4 bv4 = *(const float4*)(Bptr + (size_t)kk * DD);
        __syncthreads();
        As[acol + 0][arow] = av.x;
        As[acol + 1][arow] = av.y;
        As[acol + 2][arow] = av.z;
        As[acol + 3][arow] = av.w;
        *(float4*)(&Bs[brow][bcol]) = bv4;
        __syncthreads();
        #pragma unroll
        for (int k = 0; k < 8; k++) {
            float a[8], b[8];
            #pragma unroll
            for (int i = 0; i < 8; i++) a[i] = As[k][tr * 8 + i];
            #pragma unroll
            for (int j = 0; j < 8; j++) b[j] = Bs[k][tc * 8 + j];
            #pragma unroll
            for (int i = 0; i < 8; i++)
                #pragma unroll
                for (int j = 0; j < 8; j++)
                    acc[i][j] = fmaf(a[i], b[j], acc[i][j]);
        }
    }

    // Epilogue: write into head-split scratch [z][b*H+h][t][hd]
    const int bidx = bm >> 4;   // 128-row tiles: 16 tiles per batch (T=2048)
    #pragma unroll
    for (int i = 0; i < 8; i++) {
        int m = bm * 128 + tr * 8 + i;
        int t = m & (TT - 1);
        #pragma unroll
        for (int j = 0; j < 8; j++) {
            int col = bn * 128 + tc * 8 + j;
            int h  = col >> 6;
            int hd = col & 63;
            g_qkv[(((size_t)z * BHH + bidx * HH + h) * TT + t) * HDD + hd] =
                acc[i][j] + bias[col];
        }
    }
}

// ---------------------------------------------------------------------------
// Flash attention: one block = one (b,h) and 64 query rows.
// Loops over 32-key tiles with online softmax. O accumulated in registers.
// Thread layout: 16x16; each thread owns 4 query rows.
//   S pass:  s[4 rows][2 key cols]   (64x32 S tile)
//   PV pass: o[4 rows][4 hd cols]    (64x64 O tile)
// ---------------------------------------------------------------------------
__global__ void __launch_bounds__(256) attn_kernel(float* __restrict__ out)
{
    __shared__ float Qs[64 * 64];    // Q tile, pre-scaled, stride 64
    __shared__ float KPs[32 * 65];   // K tile (stride 65), reused as P (stride 32)
    __shared__ float Vs[32 * 64];    // V tile, stride 64

    const int tid = threadIdx.x;
    const int ty = tid >> 4;   // 0..15 -> query rows ty*4..ty*4+3
    const int tx = tid & 15;   // 0..15
    const int bh = blockIdx.y;
    const int q0 = blockIdx.x * 64;

    const float* Qg = g_qkv + ((size_t)(0 * BHH + bh) * TT + q0) * HDD;
    const float* Kg = g_qkv + ((size_t)(1 * BHH + bh) * TT) * HDD;
    const float* Vg = g_qkv + ((size_t)(2 * BHH + bh) * TT) * HDD;

    const float scale = 0.125f;   // 1/sqrt(64)

    // Load Q tile once, pre-scaled.
    for (int i = tid; i < 64 * 16; i += 256) {
        int r = i >> 4, c4 = (i & 15) * 4;
        float4 v = *(const float4*)(Qg + (size_t)r * 64 + c4);
        Qs[r * 64 + c4 + 0] = v.x * scale;
        Qs[r * 64 + c4 + 1] = v.y * scale;
        Qs[r * 64 + c4 + 2] = v.z * scale;
        Qs[r * 64 + c4 + 3] = v.w * scale;
    }

    float m_[4], l_[4];
    float o[4][4] = {};
    #pragma unroll
    for (int i = 0; i < 4; i++) { m_[i] = -1e30f; l_[i] = 0.f; }

    for (int jt = 0; jt < TT / 32; jt++) {
        __syncthreads();   // prior PV pass done; safe to overwrite KPs/Vs
        // Load K tile (stride 65) and V tile (stride 64)
        for (int i = tid; i < 32 * 16; i += 256) {
            int r = i >> 4, c4 = (i & 15) * 4;
            float4 kv = *(const float4*)(Kg + (size_t)(jt * 32 + r) * 64 + c4);
            KPs[r * 65 + c4 + 0] = kv.x;
            KPs[r * 65 + c4 + 1] = kv.y;
            KPs[r * 65 + c4 + 2] = kv.z;
            KPs[r * 65 + c4 + 3] = kv.w;
            float4 vv = *(const float4*)(Vg + (size_t)(jt * 32 + r) * 64 + c4);
            *(float4*)(&Vs[r * 64 + c4]) = vv;
        }
        __syncthreads();

        // S = (Q*scale) @ K^T : 64x32 tile, 4x2 per thread
        float s[4][2] = {};
        #pragma unroll 8
        for (int d = 0; d < 64; d++) {
            float q[4], k2[2];
            #pragma unroll
            for (int i = 0; i < 4; i++) q[i] = Qs[(ty * 4 + i) * 64 + d];
            #pragma unroll
            for (int j = 0; j < 2; j++) k2[j] = KPs[(tx * 2 + j) * 65 + d];
            #pragma unroll
            for (int i = 0; i < 4; i++)
                #pragma unroll
                for (int j = 0; j < 2; j++)
                    s[i][j] = fmaf(q[i], k2[j], s[i][j]);
        }

        // Online softmax: row stats shared by 16 tx threads (shfl width 16)
        float p[4][2];
        #pragma unroll
        for (int i = 0; i < 4; i++) {
            float mx = fmaxf(s[i][0], s[i][1]);
            #pragma unroll
            for (int off = 8; off > 0; off >>= 1)
                mx = fmaxf(mx, __shfl_xor_sync(0xffffffffu, mx, off, 16));
            float mnew  = fmaxf(m_[i], mx);
            float alpha = __expf(m_[i] - mnew);
            float ps = 0.f;
            #pragma unroll
            for (int j = 0; j < 2; j++) {
                p[i][j] = __expf(s[i][j] - mnew);
                ps += p[i][j];
            }
            #pragma unroll
            for (int off = 8; off > 0; off >>= 1)
                ps += __shfl_xor_sync(0xffffffffu, ps, off, 16);
            l_[i] = l_[i] * alpha + ps;
            m_[i] = mnew;
            #pragma unroll
            for (int j = 0; j < 4; j++) o[i][j] *= alpha;
        }

        __syncthreads();   // everyone done reading K rows before P overwrite
        // Write P (64x32, stride 32) into KPs
        #pragma unroll
        for (int i = 0; i < 4; i++)
            #pragma unroll
            for (int j = 0; j < 2; j++)
                KPs[(ty * 4 + i) * 32 + tx * 2 + j] = p[i][j];
        __syncthreads();

        // O += P @ V : 64x64, 4x4 per thread
        #pragma unroll 4
        for (int k = 0; k < 32; k++) {
            float pp[4], vv[4];
            #pragma unroll
            for (int i = 0; i < 4; i++) pp[i] = KPs[(ty * 4 + i) * 32 + k];
            #pragma unroll
            for (int j = 0; j < 4; j++) vv[j] = Vs[k * 64 + tx * 4 + j];
            #pragma unroll
            for (int i = 0; i < 4; i++)
                #pragma unroll
                for (int j = 0; j < 4; j++)
                    o[i][j] = fmaf(pp[i], vv[j], o[i][j]);
        }
    }

    // Normalize and write out in [B][T][D] layout
    const int b = bh >> 4, h = bh & 15;
    #pragma unroll
    for (int i = 0; i < 4; i++) {
        float inv = 1.0f / l_[i];
        int t = q0 + ty * 4 + i;
        #pragma unroll
        for (int j = 0; j < 4; j++) {
            int col = h * 64 + tx * 4 + j;
            out[((size_t)b * TT + t) * DD + col] = o[i][j] * inv;
        }
    }
}

// ---------------------------------------------------------------------------
extern "C" void kernel_launch(void* const* d_in, const int* in_sizes, int n_in,
                              void* d_out, int out_size)
{
    const float* x  = (const float*)d_in[0];
    const float* Wq = (const float*)d_in[1];
    const float* bq = (const float*)d_in[2];
    const float* Wk = (const float*)d_in[3];
    const float* bk = (const float*)d_in[4];
    const float* Wv = (const float*)d_in[5];
    const float* bv = (const float*)d_in[6];
    float* out = (float*)d_out;

    // QKV projections: grid (N/128, M/128, 3)
    qkv_gemm_kernel<<<dim3(DD / 128, BB * TT / 128, 3), 256>>>(
        x, Wq, bq, Wk, bk, Wv, bv);

    // Attention: grid (T/64 query tiles, B*H heads)
    attn_kernel<<<dim3(TT / 64, BHH), 256>>>(out);
}

// round 9
// speedup vs baseline: 1.4742x; 1.4742x over previous
#include <cuda_runtime.h>
#include <cuda_bf16.h>
#include <math.h>
#include <stdint.h>

#define BB  4
#define TT  2048
#define DD  1024
#define HH  16
#define HDD 64
#define BHH (BB*HH)

// QKV scratch in head-split layout: [3][B*H][T][HD]
__device__ float g_qkv[3ULL * BHH * TT * HDD];
// bf16 hi/lo split operands
__device__ __nv_bfloat16 g_Xh[(size_t)BB * TT * DD];
__device__ __nv_bfloat16 g_Xl[(size_t)BB * TT * DD];
__device__ __nv_bfloat16 g_Wh[3][(size_t)DD * DD];   // transposed: [n][k]
__device__ __nv_bfloat16 g_Wl[3][(size_t)DD * DD];

// ---------------------------------------------------------------------------
// PTX helpers: mma.sync / ldmatrix / cp.async (all plain sm_80+ PTX)
// ---------------------------------------------------------------------------
__device__ __forceinline__ uint32_t smem_u32(const void* p) {
    uint32_t a;
    asm("{ .reg .u64 t; cvta.to.shared.u64 t, %1; cvt.u32.u64 %0, t; }"
        : "=r"(a) : "l"(p));
    return a;
}

__device__ __forceinline__ void ldsm4(uint32_t* r, uint32_t addr) {
    asm volatile("ldmatrix.sync.aligned.m8n8.x4.shared.b16 {%0,%1,%2,%3}, [%4];"
                 : "=r"(r[0]), "=r"(r[1]), "=r"(r[2]), "=r"(r[3]) : "r"(addr));
}

__device__ __forceinline__ void mma16816(float* d, const uint32_t* a,
                                         const uint32_t* b) {
    asm volatile(
        "mma.sync.aligned.m16n8k16.row.col.f32.bf16.bf16.f32 "
        "{%0,%1,%2,%3}, {%4,%5,%6,%7}, {%8,%9}, {%0,%1,%2,%3};"
        : "+f"(d[0]), "+f"(d[1]), "+f"(d[2]), "+f"(d[3])
        : "r"(a[0]), "r"(a[1]), "r"(a[2]), "r"(a[3]), "r"(b[0]), "r"(b[1]));
}

#define CP_ASYNC16(smem_addr, gptr) \
    asm volatile("cp.async.cg.shared.global [%0], [%1], 16;" \
                 :: "r"(smem_addr), "l"(gptr) : "memory")
#define CP_COMMIT() asm volatile("cp.async.commit_group;" ::: "memory")
#define CP_WAIT(n)  asm volatile("cp.async.wait_group %0;" :: "n"(n) : "memory")

// ---------------------------------------------------------------------------
// Converters: fp32 -> bf16 hi/lo split
// ---------------------------------------------------------------------------
__global__ void __launch_bounds__(256) convert_x_kernel(const float* __restrict__ x)
{
    size_t i = ((size_t)blockIdx.x * 256 + threadIdx.x) * 4;
    float4 v = *(const float4*)(x + i);
    __nv_bfloat16 h0 = __float2bfloat16(v.x), h1 = __float2bfloat16(v.y);
    __nv_bfloat16 h2 = __float2bfloat16(v.z), h3 = __float2bfloat16(v.w);
    __nv_bfloat16 l0 = __float2bfloat16(v.x - __bfloat162float(h0));
    __nv_bfloat16 l1 = __float2bfloat16(v.y - __bfloat162float(h1));
    __nv_bfloat16 l2 = __float2bfloat16(v.z - __bfloat162float(h2));
    __nv_bfloat16 l3 = __float2bfloat16(v.w - __bfloat162float(h3));
    uint2 uh, ul;
    uh.x = (uint32_t)__bfloat16_as_ushort(h0) | ((uint32_t)__bfloat16_as_ushort(h1) << 16);
    uh.y = (uint32_t)__bfloat16_as_ushort(h2) | ((uint32_t)__bfloat16_as_ushort(h3) << 16);
    ul.x = (uint32_t)__bfloat16_as_ushort(l0) | ((uint32_t)__bfloat16_as_ushort(l1) << 16);
    ul.y = (uint32_t)__bfloat16_as_ushort(l2) | ((uint32_t)__bfloat16_as_ushort(l3) << 16);
    *(uint2*)(g_Xh + i) = uh;
    *(uint2*)(g_Xl + i) = ul;
}

// Transpose + split: g_W{h,l}[z][n][k] = split(W[k][n])
__global__ void __launch_bounds__(256) convert_w_kernel(
    const float* __restrict__ Wq, const float* __restrict__ Wk,
    const float* __restrict__ Wv)
{
    __shared__ float tile[32][33];
    const int z = blockIdx.z;
    const float* W = (z == 0) ? Wq : (z == 1) ? Wk : Wv;
    const int n0 = blockIdx.x * 32, k0 = blockIdx.y * 32;
    const int tx = threadIdx.x, ty = threadIdx.y;   // 32 x 8

    #pragma unroll
    for (int r = ty; r < 32; r += 8)
        tile[r][tx] = W[(size_t)(k0 + r) * DD + n0 + tx];
    __syncthreads();

    __nv_bfloat16* oh = g_Wh[z];
    __nv_bfloat16* ol = g_Wl[z];
    #pragma unroll
    for (int r = ty; r < 32; r += 8) {
        float v = tile[tx][r];                       // W[k0+tx][n0+r]
        __nv_bfloat16 h = __float2bfloat16(v);
        __nv_bfloat16 l = __float2bfloat16(v - __bfloat162float(h));
        size_t o = (size_t)(n0 + r) * DD + k0 + tx;
        oh[o] = h;
        ol[o] = l;
    }
}

// ---------------------------------------------------------------------------
// QKV projection via mma.sync bf16 (3-pass hi/lo error correction)
// Block tile 128x128, 8 warps (2x4), warp tile 64x32, K chunk 64.
// Double-buffered cp.async smem, XOR-swizzled 128B rows for ldmatrix.
// ---------------------------------------------------------------------------
#define TILE_BYTES 16384                 // 128 rows x 128 bytes (128x64 bf16)
#define BUF_BYTES  (4 * TILE_BYTES)      // Ah, Al, Bh, Bl
#define GEMM_SMEM  (2 * BUF_BYTES)       // 131072

__global__ void __launch_bounds__(256, 1)
qkv_mma_kernel(const float* __restrict__ bq, const float* __restrict__ bk,
               const float* __restrict__ bv)
{
    extern __shared__ __align__(1024) char smem[];
    const uint32_t sb = smem_u32(smem);

    const int tid  = threadIdx.x;
    const int wid  = tid >> 5;
    const int lane = tid & 31;

    const int bn = blockIdx.x;   // 8 N-tiles
    const int bm = blockIdx.y;   // 64 M-tiles
    const int z  = blockIdx.z;

    const __nv_bfloat16* pAh = g_Xh + (size_t)(bm * 128) * DD;
    const __nv_bfloat16* pAl = g_Xl + (size_t)(bm * 128) * DD;
    const __nv_bfloat16* pBh = g_Wh[z] + (size_t)(bn * 128) * DD;
    const __nv_bfloat16* pBl = g_Wl[z] + (size_t)(bn * 128) * DD;

    // cp.async mapping: thread -> (row lr + 32*i, 16B chunk lc), swizzled col
    const int lr = tid >> 3;             // 0..31
    const int lc = tid & 7;              // 0..7
    const int sc = ((lc ^ (lr & 7)) << 4);

    // warp tile origin
    const int wm = (wid >> 2) * 64;
    const int wn = (wid & 3) * 32;

    // ldmatrix per-thread geometry (swizzle XOR key is lane&7 for all rows)
    const int arow_off = (lane & 7) + ((lane >> 3) & 1) * 8;
    const int acol     = (lane >> 4);          // 0/1 -> k chunk +0/+1
    const int brow_off = (lane & 7) + ((lane >> 4) << 3);
    const int bcol     = (lane >> 3) & 1;
    const int sxor     = lane & 7;

    float acc[4][4][4] = {};

    // ---- pipeline: issue chunk c into buffer c&1 ----
    auto issue = [&](int c) {
        const int kk  = c * 64;
        const uint32_t base = sb + (uint32_t)(c & 1) * BUF_BYTES;
        #pragma unroll
        for (int i = 0; i < 4; i++) {
            const int r = lr + 32 * i;
            const size_t go = (size_t)r * DD + kk + lc * 8;
            const uint32_t so = (uint32_t)(r * 128 + sc);
            CP_ASYNC16(base + 0 * TILE_BYTES + so, pAh + go);
            CP_ASYNC16(base + 1 * TILE_BYTES + so, pAl + go);
            CP_ASYNC16(base + 2 * TILE_BYTES + so, pBh + go);
            CP_ASYNC16(base + 3 * TILE_BYTES + so, pBl + go);
        }
    };

    issue(0);
    CP_COMMIT();

    for (int c = 0; c < 16; c++) {
        if (c + 1 < 16) {
            issue(c + 1);
            CP_COMMIT();
            CP_WAIT(1);
        } else {
            CP_WAIT(0);
        }
        __syncthreads();

        const uint32_t tb = sb + (uint32_t)(c & 1) * BUF_BYTES;
        #pragma unroll
        for (int kb = 0; kb < 4; kb++) {
            uint32_t a_h[4][4], a_l[4][4], b_h[4][2], b_l[4][2];
            const uint32_t aoff = (uint32_t)((((2 * kb + acol) ^ sxor) << 4));
            const uint32_t boff = (uint32_t)((((2 * kb + bcol) ^ sxor) << 4));
            #pragma unroll
            for (int mt = 0; mt < 4; mt++) {
                const uint32_t ra = (uint32_t)((wm + mt * 16 + arow_off) * 128);
                ldsm4(a_h[mt], tb + 0 * TILE_BYTES + ra + aoff);
                ldsm4(a_l[mt], tb + 1 * TILE_BYTES + ra + aoff);
            }
            #pragma unroll
            for (int np = 0; np < 2; np++) {
                const uint32_t rb = (uint32_t)((wn + np * 16 + brow_off) * 128);
                uint32_t r4[4];
                ldsm4(r4, tb + 2 * TILE_BYTES + rb + boff);
                b_h[2 * np][0] = r4[0]; b_h[2 * np][1] = r4[1];
                b_h[2 * np + 1][0] = r4[2]; b_h[2 * np + 1][1] = r4[3];
                ldsm4(r4, tb + 3 * TILE_BYTES + rb + boff);
                b_l[2 * np][0] = r4[0]; b_l[2 * np][1] = r4[1];
                b_l[2 * np + 1][0] = r4[2]; b_l[2 * np + 1][1] = r4[3];
            }
            #pragma unroll
            for (int mt = 0; mt < 4; mt++)
                #pragma unroll
                for (int nt = 0; nt < 4; nt++) {
                    mma16816(acc[mt][nt], a_h[mt], b_h[nt]);
                    mma16816(acc[mt][nt], a_h[mt], b_l[nt]);
                    mma16816(acc[mt][nt], a_l[mt], b_h[nt]);
                }
        }
        __syncthreads();
    }

    // ---- epilogue: + bias, scatter head-split ----
    const float* bias = (z == 0) ? bq : (z == 1) ? bk : bv;
    #pragma unroll
    for (int mt = 0; mt < 4; mt++) {
        #pragma unroll
        for (int nt = 0; nt < 4; nt++) {
            const int col = bn * 128 + wn + nt * 8 + (lane & 3) * 2;
            const int h = col >> 6, hd = col & 63;
            const float2 bv2 = *(const float2*)(bias + col);
            const int m0 = bm * 128 + wm + mt * 16 + (lane >> 2);
            #pragma unroll
            for (int half = 0; half < 2; half++) {
                const int m = m0 + half * 8;
                const int t = m & (TT - 1);
                const int bidx = m >> 11;
                float2 v;
                v.x = acc[mt][nt][half * 2 + 0] + bv2.x;
                v.y = acc[mt][nt][half * 2 + 1] + bv2.y;
                *(float2*)(g_qkv + (((size_t)z * BHH + bidx * HH + h) * TT + t)
                           * HDD + hd) = v;
            }
        }
    }
}

// ---------------------------------------------------------------------------
// Flash attention (unchanged fp32 kernel)
// ---------------------------------------------------------------------------
__global__ void __launch_bounds__(256) attn_kernel(float* __restrict__ out)
{
    __shared__ float Qs[64 * 64];
    __shared__ float KPs[32 * 65];
    __shared__ float Vs[32 * 64];

    const int tid = threadIdx.x;
    const int ty = tid >> 4;
    const int tx = tid & 15;
    const int bh = blockIdx.y;
    const int q0 = blockIdx.x * 64;

    const float* Qg = g_qkv + ((size_t)(0 * BHH + bh) * TT + q0) * HDD;
    const float* Kg = g_qkv + ((size_t)(1 * BHH + bh) * TT) * HDD;
    const float* Vg = g_qkv + ((size_t)(2 * BHH + bh) * TT) * HDD;

    const float scale = 0.125f;

    for (int i = tid; i < 64 * 16; i += 256) {
        int r = i >> 4, c4 = (i & 15) * 4;
        float4 v = *(const float4*)(Qg + (size_t)r * 64 + c4);
        Qs[r * 64 + c4 + 0] = v.x * scale;
        Qs[r * 64 + c4 + 1] = v.y * scale;
        Qs[r * 64 + c4 + 2] = v.z * scale;
        Qs[r * 64 + c4 + 3] = v.w * scale;
    }

    float m_[4], l_[4];
    float o[4][4] = {};
    #pragma unroll
    for (int i = 0; i < 4; i++) { m_[i] = -1e30f; l_[i] = 0.f; }

    for (int jt = 0; jt < TT / 32; jt++) {
        __syncthreads();
        for (int i = tid; i < 32 * 16; i += 256) {
            int r = i >> 4, c4 = (i & 15) * 4;
            float4 kv = *(const float4*)(Kg + (size_t)(jt * 32 + r) * 64 + c4);
            KPs[r * 65 + c4 + 0] = kv.x;
            KPs[r * 65 + c4 + 1] = kv.y;
            KPs[r * 65 + c4 + 2] = kv.z;
            KPs[r * 65 + c4 + 3] = kv.w;
            float4 vv = *(const float4*)(Vg + (size_t)(jt * 32 + r) * 64 + c4);
            *(float4*)(&Vs[r * 64 + c4]) = vv;
        }
        __syncthreads();

        float s[4][2] = {};
        #pragma unroll 8
        for (int d = 0; d < 64; d++) {
            float q[4], k2[2];
            #pragma unroll
            for (int i = 0; i < 4; i++) q[i] = Qs[(ty * 4 + i) * 64 + d];
            #pragma unroll
            for (int j = 0; j < 2; j++) k2[j] = KPs[(tx * 2 + j) * 65 + d];
            #pragma unroll
            for (int i = 0; i < 4; i++)
                #pragma unroll
                for (int j = 0; j < 2; j++)
                    s[i][j] = fmaf(q[i], k2[j], s[i][j]);
        }

        float p[4][2];
        #pragma unroll
        for (int i = 0; i < 4; i++) {
            float mx = fmaxf(s[i][0], s[i][1]);
            #pragma unroll
            for (int off = 8; off > 0; off >>= 1)
                mx = fmaxf(mx, __shfl_xor_sync(0xffffffffu, mx, off, 16));
            float mnew  = fmaxf(m_[i], mx);
            float alpha = __expf(m_[i] - mnew);
            float ps = 0.f;
            #pragma unroll
            for (int j = 0; j < 2; j++) {
                p[i][j] = __expf(s[i][j] - mnew);
                ps += p[i][j];
            }
            #pragma unroll
            for (int off = 8; off > 0; off >>= 1)
                ps += __shfl_xor_sync(0xffffffffu, ps, off, 16);
            l_[i] = l_[i] * alpha + ps;
            m_[i] = mnew;
            #pragma unroll
            for (int j = 0; j < 4; j++) o[i][j] *= alpha;
        }

        __syncthreads();
        #pragma unroll
        for (int i = 0; i < 4; i++)
            #pragma unroll
            for (int j = 0; j < 2; j++)
                KPs[(ty * 4 + i) * 32 + tx * 2 + j] = p[i][j];
        __syncthreads();

        #pragma unroll 4
        for (int k = 0; k < 32; k++) {
            float pp[4], vv[4];
            #pragma unroll
            for (int i = 0; i < 4; i++) pp[i] = KPs[(ty * 4 + i) * 32 + k];
            #pragma unroll
            for (int j = 0; j < 4; j++) vv[j] = Vs[k * 64 + tx * 4 + j];
            #pragma unroll
            for (int i = 0; i < 4; i++)
                #pragma unroll
                for (int j = 0; j < 4; j++)
                    o[i][j] = fmaf(pp[i], vv[j], o[i][j]);
        }
    }

    const int b = bh >> 4, h = bh & 15;
    #pragma unroll
    for (int i = 0; i < 4; i++) {
        float inv = 1.0f / l_[i];
        int t = q0 + ty * 4 + i;
        #pragma unroll
        for (int j = 0; j < 4; j++) {
            int col = h * 64 + tx * 4 + j;
            out[((size_t)b * TT + t) * DD + col] = o[i][j] * inv;
        }
    }
}

// ---------------------------------------------------------------------------
extern "C" void kernel_launch(void* const* d_in, const int* in_sizes, int n_in,
                              void* d_out, int out_size)
{
    const float* x  = (const float*)d_in[0];
    const float* Wq = (const float*)d_in[1];
    const float* bq = (const float*)d_in[2];
    const float* Wk = (const float*)d_in[3];
    const float* bk = (const float*)d_in[4];
    const float* Wv = (const float*)d_in[5];
    const float* bv = (const float*)d_in[6];
    float* out = (float*)d_out;

    static int smem_set = 0;
    if (!smem_set) {
        cudaFuncSetAttribute(qkv_mma_kernel,
                             cudaFuncAttributeMaxDynamicSharedMemorySize,
                             GEMM_SMEM);
        smem_set = 1;
    }

    // bf16 hi/lo splits
    convert_x_kernel<<<(BB * TT * DD) / 4 / 256, 256>>>(x);
    convert_w_kernel<<<dim3(DD / 32, DD / 32, 3), dim3(32, 8)>>>(Wq, Wk, Wv);

    // QKV projections on tensor cores (HMMA): grid (N/128, M/128, 3)
    qkv_mma_kernel<<<dim3(DD / 128, BB * TT / 128, 3), 256, GEMM_SMEM>>>(bq, bk, bv);

    // Attention: grid (T/64 query tiles, B*H heads)
    attn_kernel<<<dim3(TT / 64, BHH), 256>>>(out);
}

// round 12
// speedup vs baseline: 3.9874x; 2.7049x over previous
#include <cuda_runtime.h>
#include <cuda_bf16.h>
#include <math.h>
#include <stdint.h>

#define BB  4
#define TT  2048
#define DD  1024
#define HH  16
#define HDD 64
#define BHH (BB*HH)

// bf16 hi/lo split operands for the projections
__device__ __nv_bfloat16 g_Xh[(size_t)BB * TT * DD];
__device__ __nv_bfloat16 g_Xl[(size_t)BB * TT * DD];
__device__ __nv_bfloat16 g_Wh[3][(size_t)DD * DD];   // transposed: [n][k]
__device__ __nv_bfloat16 g_Wl[3][(size_t)DD * DD];
// Q/K/V head-split hi/lo: [bh][t][hd]   (Q pre-scaled by 1/8)
__device__ __nv_bfloat16 g_Qh[(size_t)BHH * TT * HDD];
__device__ __nv_bfloat16 g_Ql[(size_t)BHH * TT * HDD];
__device__ __nv_bfloat16 g_Kh[(size_t)BHH * TT * HDD];
__device__ __nv_bfloat16 g_Kl[(size_t)BHH * TT * HDD];
__device__ __nv_bfloat16 g_Vh[(size_t)BHH * TT * HDD];
__device__ __nv_bfloat16 g_Vl[(size_t)BHH * TT * HDD];

// ---------------------------------------------------------------------------
// PTX helpers: mma.sync / ldmatrix / cp.async
// ---------------------------------------------------------------------------
__device__ __forceinline__ uint32_t smem_u32(const void* p) {
    uint32_t a;
    asm("{ .reg .u64 t; cvta.to.shared.u64 t, %1; cvt.u32.u64 %0, t; }"
        : "=r"(a) : "l"(p));
    return a;
}
__device__ __forceinline__ void ldsm4(uint32_t* r, uint32_t addr) {
    asm volatile("ldmatrix.sync.aligned.m8n8.x4.shared.b16 {%0,%1,%2,%3}, [%4];"
                 : "=r"(r[0]), "=r"(r[1]), "=r"(r[2]), "=r"(r[3]) : "r"(addr));
}
__device__ __forceinline__ void ldsm4t(uint32_t* r, uint32_t addr) {
    asm volatile("ldmatrix.sync.aligned.m8n8.x4.trans.shared.b16 {%0,%1,%2,%3}, [%4];"
                 : "=r"(r[0]), "=r"(r[1]), "=r"(r[2]), "=r"(r[3]) : "r"(addr));
}
__device__ __forceinline__ void mma16816(float* d, const uint32_t* a,
                                         const uint32_t* b) {
    asm volatile(
        "mma.sync.aligned.m16n8k16.row.col.f32.bf16.bf16.f32 "
        "{%0,%1,%2,%3}, {%4,%5,%6,%7}, {%8,%9}, {%0,%1,%2,%3};"
        : "+f"(d[0]), "+f"(d[1]), "+f"(d[2]), "+f"(d[3])
        : "r"(a[0]), "r"(a[1]), "r"(a[2]), "r"(a[3]), "r"(b[0]), "r"(b[1]));
}
#define CP_ASYNC16(smem_addr, gptr) \
    asm volatile("cp.async.cg.shared.global [%0], [%1], 16;" \
                 :: "r"(smem_addr), "l"(gptr) : "memory")
#define CP_COMMIT() asm volatile("cp.async.commit_group;" ::: "memory")
#define CP_WAIT(n)  asm volatile("cp.async.wait_group %0;" :: "n"(n) : "memory")

__device__ __forceinline__ uint32_t pack_bf16(float a, float b) {
    __nv_bfloat162 h = __floats2bfloat162_rn(a, b);
    return *(uint32_t*)&h;
}

// ---------------------------------------------------------------------------
// Converters: fp32 -> bf16 hi/lo split
// ---------------------------------------------------------------------------
__global__ void __launch_bounds__(256) convert_x_kernel(const float* __restrict__ x)
{
    size_t i = ((size_t)blockIdx.x * 256 + threadIdx.x) * 4;
    float4 v = *(const float4*)(x + i);
    __nv_bfloat16 h0 = __float2bfloat16(v.x), h1 = __float2bfloat16(v.y);
    __nv_bfloat16 h2 = __float2bfloat16(v.z), h3 = __float2bfloat16(v.w);
    __nv_bfloat16 l0 = __float2bfloat16(v.x - __bfloat162float(h0));
    __nv_bfloat16 l1 = __float2bfloat16(v.y - __bfloat162float(h1));
    __nv_bfloat16 l2 = __float2bfloat16(v.z - __bfloat162float(h2));
    __nv_bfloat16 l3 = __float2bfloat16(v.w - __bfloat162float(h3));
    uint2 uh, ul;
    uh.x = (uint32_t)__bfloat16_as_ushort(h0) | ((uint32_t)__bfloat16_as_ushort(h1) << 16);
    uh.y = (uint32_t)__bfloat16_as_ushort(h2) | ((uint32_t)__bfloat16_as_ushort(h3) << 16);
    ul.x = (uint32_t)__bfloat16_as_ushort(l0) | ((uint32_t)__bfloat16_as_ushort(l1) << 16);
    ul.y = (uint32_t)__bfloat16_as_ushort(l2) | ((uint32_t)__bfloat16_as_ushort(l3) << 16);
    *(uint2*)(g_Xh + i) = uh;
    *(uint2*)(g_Xl + i) = ul;
}

__global__ void __launch_bounds__(256) convert_w_kernel(
    const float* __restrict__ Wq, const float* __restrict__ Wk,
    const float* __restrict__ Wv)
{
    __shared__ float tile[32][33];
    const int z = blockIdx.z;
    const float* W = (z == 0) ? Wq : (z == 1) ? Wk : Wv;
    const int n0 = blockIdx.x * 32, k0 = blockIdx.y * 32;
    const int tx = threadIdx.x, ty = threadIdx.y;

    #pragma unroll
    for (int r = ty; r < 32; r += 8)
        tile[r][tx] = W[(size_t)(k0 + r) * DD + n0 + tx];
    __syncthreads();

    __nv_bfloat16* oh = g_Wh[z];
    __nv_bfloat16* ol = g_Wl[z];
    #pragma unroll
    for (int r = ty; r < 32; r += 8) {
        float v = tile[tx][r];
        __nv_bfloat16 h = __float2bfloat16(v);
        __nv_bfloat16 l = __float2bfloat16(v - __bfloat162float(h));
        size_t o = (size_t)(n0 + r) * DD + k0 + tx;
        oh[o] = h;
        ol[o] = l;
    }
}

// ---------------------------------------------------------------------------
// QKV projection via mma.sync bf16 (3-pass hi/lo). Epilogue writes bf16 hi/lo
// Q/K/V head-split; Q pre-scaled by 0.125.
// ---------------------------------------------------------------------------
#define TILE_BYTES 16384
#define BUF_BYTES  (4 * TILE_BYTES)
#define GEMM_SMEM  (2 * BUF_BYTES)

__global__ void __launch_bounds__(256, 1)
qkv_mma_kernel(const float* __restrict__ bq, const float* __restrict__ bk,
               const float* __restrict__ bv)
{
    extern __shared__ __align__(1024) char smem[];
    const uint32_t sb = smem_u32(smem);

    const int tid  = threadIdx.x;
    const int wid  = tid >> 5;
    const int lane = tid & 31;

    const int bn = blockIdx.x;
    const int bm = blockIdx.y;
    const int z  = blockIdx.z;

    const __nv_bfloat16* pAh = g_Xh + (size_t)(bm * 128) * DD;
    const __nv_bfloat16* pAl = g_Xl + (size_t)(bm * 128) * DD;
    const __nv_bfloat16* pBh = g_Wh[z] + (size_t)(bn * 128) * DD;
    const __nv_bfloat16* pBl = g_Wl[z] + (size_t)(bn * 128) * DD;

    const int lr = tid >> 3;
    const int lc = tid & 7;
    const int sc = ((lc ^ (lr & 7)) << 4);

    const int wm = (wid >> 2) * 64;
    const int wn = (wid & 3) * 32;

    const int arow_off = lane & 15;
    const int acol     = lane >> 4;
    const int brow_off = (lane & 7) + ((lane >> 4) << 3);
    const int bcol     = (lane >> 3) & 1;
    const int sxor     = lane & 7;

    float acc[4][4][4] = {};

    auto issue = [&](int c) {
        const int kk  = c * 64;
        const uint32_t base = sb + (uint32_t)(c & 1) * BUF_BYTES;
        #pragma unroll
        for (int i = 0; i < 4; i++) {
            const int r = lr + 32 * i;
            const size_t go = (size_t)r * DD + kk + lc * 8;
            const uint32_t so = (uint32_t)(r * 128 + sc);
            CP_ASYNC16(base + 0 * TILE_BYTES + so, pAh + go);
            CP_ASYNC16(base + 1 * TILE_BYTES + so, pAl + go);
            CP_ASYNC16(base + 2 * TILE_BYTES + so, pBh + go);
            CP_ASYNC16(base + 3 * TILE_BYTES + so, pBl + go);
        }
    };

    issue(0);
    CP_COMMIT();

    for (int c = 0; c < 16; c++) {
        if (c + 1 < 16) {
            issue(c + 1);
            CP_COMMIT();
            CP_WAIT(1);
        } else {
            CP_WAIT(0);
        }
        __syncthreads();

        const uint32_t tb = sb + (uint32_t)(c & 1) * BUF_BYTES;
        #pragma unroll
        for (int kb = 0; kb < 4; kb++) {
            uint32_t a_h[4][4], a_l[4][4], b_h[4][2], b_l[4][2];
            const uint32_t aoff = (uint32_t)(((2 * kb + acol) ^ sxor) << 4);
            const uint32_t boff = (uint32_t)(((2 * kb + bcol) ^ sxor) << 4);
            #pragma unroll
            for (int mt = 0; mt < 4; mt++) {
                const uint32_t ra = (uint32_t)((wm + mt * 16 + arow_off) * 128);
                ldsm4(a_h[mt], tb + 0 * TILE_BYTES + ra + aoff);
                ldsm4(a_l[mt], tb + 1 * TILE_BYTES + ra + aoff);
            }
            #pragma unroll
            for (int np = 0; np < 2; np++) {
                const uint32_t rb = (uint32_t)((wn + np * 16 + brow_off) * 128);
                uint32_t r4[4];
                ldsm4(r4, tb + 2 * TILE_BYTES + rb + boff);
                b_h[2 * np][0] = r4[0]; b_h[2 * np][1] = r4[1];
                b_h[2 * np + 1][0] = r4[2]; b_h[2 * np + 1][1] = r4[3];
                ldsm4(r4, tb + 3 * TILE_BYTES + rb + boff);
                b_l[2 * np][0] = r4[0]; b_l[2 * np][1] = r4[1];
                b_l[2 * np + 1][0] = r4[2]; b_l[2 * np + 1][1] = r4[3];
            }
            #pragma unroll
            for (int mt = 0; mt < 4; mt++)
                #pragma unroll
                for (int nt = 0; nt < 4; nt++) {
                    mma16816(acc[mt][nt], a_h[mt], b_h[nt]);
                    mma16816(acc[mt][nt], a_h[mt], b_l[nt]);
                    mma16816(acc[mt][nt], a_l[mt], b_h[nt]);
                }
        }
        __syncthreads();
    }

    // ---- epilogue: + bias, optional Q scale, hi/lo split, head-split store
    const float* bias = (z == 0) ? bq : (z == 1) ? bk : bv;
    __nv_bfloat16* dsth = (z == 0) ? g_Qh : (z == 1) ? g_Kh : g_Vh;
    __nv_bfloat16* dstl = (z == 0) ? g_Ql : (z == 1) ? g_Kl : g_Vl;
    const float postscale = (z == 0) ? 0.125f : 1.0f;

    #pragma unroll
    for (int mt = 0; mt < 4; mt++) {
        #pragma unroll
        for (int nt = 0; nt < 4; nt++) {
            const int col = bn * 128 + wn + nt * 8 + (lane & 3) * 2;
            const int h = col >> 6, hd = col & 63;
            const float2 bv2 = *(const float2*)(bias + col);
            const int m0 = bm * 128 + wm + mt * 16 + (lane >> 2);
            #pragma unroll
            for (int half = 0; half < 2; half++) {
                const int m = m0 + half * 8;
                const int t = m & (TT - 1);
                const int bidx = m >> 11;
                const size_t off =
                    (((size_t)bidx * HH + h) * TT + t) * HDD + hd;
                float v0 = (acc[mt][nt][half * 2 + 0] + bv2.x) * postscale;
                float v1 = (acc[mt][nt][half * 2 + 1] + bv2.y) * postscale;
                __nv_bfloat16 h0 = __float2bfloat16(v0);
                __nv_bfloat16 h1 = __float2bfloat16(v1);
                __nv_bfloat16 e0 = __float2bfloat16(v0 - __bfloat162float(h0));
                __nv_bfloat16 e1 = __float2bfloat16(v1 - __bfloat162float(h1));
                *(uint32_t*)(dsth + off) =
                    (uint32_t)__bfloat16_as_ushort(h0) |
                    ((uint32_t)__bfloat16_as_ushort(h1) << 16);
                *(uint32_t*)(dstl + off) =
                    (uint32_t)__bfloat16_as_ushort(e0) |
                    ((uint32_t)__bfloat16_as_ushort(e1) << 16);
            }
        }
    }
}

// ---------------------------------------------------------------------------
// Flash attention on mma.sync bf16 (3-pass hi/lo for both S and PV).
// Block: 256 threads / 8 warps, 128 queries, 64-key tiles, double-buffered.
// Smem: Qh/Ql (2x16KB) + 2 x (Kh,Kl,Vh,Vl 4x8KB) = 96KB.
// ---------------------------------------------------------------------------
#define AT_QBYTES 16384                    // 128 rows x 128B
#define AT_KVOFF  (2 * AT_QBYTES)          // 32768
#define AT_KVBUF  32768                    // 4 x 8KB
#define ATT_SMEM  (AT_KVOFF + 2 * AT_KVBUF)

__global__ void __launch_bounds__(256, 1)
attn_mma_kernel(float* __restrict__ out)
{
    extern __shared__ __align__(1024) char smem[];
    const uint32_t sb = smem_u32(smem);

    const int tid  = threadIdx.x;
    const int wid  = tid >> 5;
    const int lane = tid & 31;

    const int bh = blockIdx.y;
    const int q0 = blockIdx.x * 128;

    const __nv_bfloat16* pQh = g_Qh + ((size_t)bh * TT + q0) * HDD;
    const __nv_bfloat16* pQl = g_Ql + ((size_t)bh * TT + q0) * HDD;
    const __nv_bfloat16* pKh = g_Kh + (size_t)bh * TT * HDD;
    const __nv_bfloat16* pKl = g_Kl + (size_t)bh * TT * HDD;
    const __nv_bfloat16* pVh = g_Vh + (size_t)bh * TT * HDD;
    const __nv_bfloat16* pVl = g_Vl + (size_t)bh * TT * HDD;

    // ---- load Q tile (hi/lo) into smem
    {
        const int row = tid >> 1;
        const int c0  = (tid & 1) * 4;
        #pragma unroll
        for (int i = 0; i < 4; i++) {
            const int ch = c0 + i;
            const uint32_t so = (uint32_t)(row * 128 + ((ch ^ (row & 7)) << 4));
            const size_t go = (size_t)row * HDD + ch * 8;
            CP_ASYNC16(sb + so, pQh + go);
            CP_ASYNC16(sb + AT_QBYTES + so, pQl + go);
        }
    }
    CP_COMMIT();

    const int lr = tid >> 3;
    const int lc = tid & 7;
    auto issue_kv = [&](int jt) {
        const uint32_t base = sb + AT_KVOFF + (uint32_t)(jt & 1) * AT_KVBUF;
        const size_t g0 = (size_t)(jt * 64) * HDD;
        #pragma unroll
        for (int i = 0; i < 2; i++) {
            const int r = lr + 32 * i;
            const uint32_t so = (uint32_t)(r * 128 + ((lc ^ (r & 7)) << 4));
            const size_t go = g0 + (size_t)r * HDD + lc * 8;
            CP_ASYNC16(base + 0 * 8192 + so, pKh + go);
            CP_ASYNC16(base + 1 * 8192 + so, pKl + go);
            CP_ASYNC16(base + 2 * 8192 + so, pVh + go);
            CP_ASYNC16(base + 3 * 8192 + so, pVl + go);
        }
    };

    issue_kv(0);
    CP_COMMIT();

    const int wm = wid * 16;                    // warp's 16 query rows
    const int arow_off = lane & 15;
    const int acol     = lane >> 4;
    const int brow_off = (lane & 7) + ((lane >> 4) << 3);
    const int bcol     = (lane >> 3) & 1;
    const int sxor     = lane & 7;

    float m0 = -1e30f, m1 = -1e30f, l0 = 0.f, l1 = 0.f;
    float o[8][4] = {};

    for (int jt = 0; jt < TT / 64; jt++) {
        if (jt + 1 < TT / 64) {
            issue_kv(jt + 1);
            CP_COMMIT();
            CP_WAIT(1);
        } else {
            CP_WAIT(0);
        }
        __syncthreads();

        const uint32_t kvb = sb + AT_KVOFF + (uint32_t)(jt & 1) * AT_KVBUF;

        // ---- S = Q @ K^T (3-pass hi/lo), 16x64 per warp
        float s[8][4] = {};
        #pragma unroll
        for (int kb = 0; kb < 4; kb++) {
            uint32_t qh[4], ql[4];
            const uint32_t aoff = (uint32_t)(((2 * kb + acol) ^ sxor) << 4);
            const uint32_t ra   = (uint32_t)((wm + arow_off) * 128);
            ldsm4(qh, sb + ra + aoff);
            ldsm4(ql, sb + AT_QBYTES + ra + aoff);
            const uint32_t boff = (uint32_t)(((2 * kb + bcol) ^ sxor) << 4);
            #pragma unroll
            for (int np = 0; np < 4; np++) {
                const uint32_t rb = (uint32_t)((np * 16 + brow_off) * 128);
                uint32_t kh[4], kl[4];
                ldsm4(kh, kvb + 0 * 8192 + rb + boff);
                ldsm4(kl, kvb + 1 * 8192 + rb + boff);
                mma16816(s[2 * np + 0], qh, kh + 0);
                mma16816(s[2 * np + 1], qh, kh + 2);
                mma16816(s[2 * np + 0], qh, kl + 0);
                mma16816(s[2 * np + 1], qh, kl + 2);
                mma16816(s[2 * np + 0], ql, kh + 0);
                mma16816(s[2 * np + 1], ql, kh + 2);
            }
        }

        // ---- online softmax (rows r=lane>>2 and r+8)
        float mx0 = -1e30f, mx1 = -1e30f;
        #pragma unroll
        for (int j = 0; j < 8; j++) {
            mx0 = fmaxf(mx0, fmaxf(s[j][0], s[j][1]));
            mx1 = fmaxf(mx1, fmaxf(s[j][2], s[j][3]));
        }
        mx0 = fmaxf(mx0, __shfl_xor_sync(0xffffffffu, mx0, 1));
        mx0 = fmaxf(mx0, __shfl_xor_sync(0xffffffffu, mx0, 2));
        mx1 = fmaxf(mx1, __shfl_xor_sync(0xffffffffu, mx1, 1));
        mx1 = fmaxf(mx1, __shfl_xor_sync(0xffffffffu, mx1, 2));

        const float mn0 = fmaxf(m0, mx0);
        const float mn1 = fmaxf(m1, mx1);
        const float al0 = __expf(m0 - mn0);
        const float al1 = __expf(m1 - mn1);

        uint32_t ph[4][4], pl[4][4];
        float rs0 = 0.f, rs1 = 0.f;
        #pragma unroll
        for (int j = 0; j < 8; j++) {
            float p0 = __expf(s[j][0] - mn0);
            float p1 = __expf(s[j][1] - mn0);
            float p2 = __expf(s[j][2] - mn1);
            float p3 = __expf(s[j][3] - mn1);
            rs0 += p0 + p1;
            rs1 += p2 + p3;
            const int kb = j >> 1, hi = (j & 1) * 2;
            ph[kb][hi + 0] = pack_bf16(p0, p1);
            ph[kb][hi + 1] = pack_bf16(p2, p3);
            float q0f = p0 - __bfloat162float(__float2bfloat16(p0));
            float q1f = p1 - __bfloat162float(__float2bfloat16(p1));
            float q2f = p2 - __bfloat162float(__float2bfloat16(p2));
            float q3f = p3 - __bfloat162float(__float2bfloat16(p3));
            pl[kb][hi + 0] = pack_bf16(q0f, q1f);
            pl[kb][hi + 1] = pack_bf16(q2f, q3f);
        }
        rs0 += __shfl_xor_sync(0xffffffffu, rs0, 1);
        rs0 += __shfl_xor_sync(0xffffffffu, rs0, 2);
        rs1 += __shfl_xor_sync(0xffffffffu, rs1, 1);
        rs1 += __shfl_xor_sync(0xffffffffu, rs1, 2);

        l0 = l0 * al0 + rs0;  m0 = mn0;
        l1 = l1 * al1 + rs1;  m1 = mn1;
        #pragma unroll
        for (int j = 0; j < 8; j++) {
            o[j][0] *= al0; o[j][1] *= al0;
            o[j][2] *= al1; o[j][3] *= al1;
        }

        // ---- O += P @ V (3-pass hi/lo). V via ldmatrix.trans.
        #pragma unroll
        for (int kb = 0; kb < 4; kb++) {
            const int vrow = kb * 16 + (lane & 15);
            const uint32_t rv = (uint32_t)(vrow * 128);
            const int vxor = vrow & 7;
            #pragma unroll
            for (int np = 0; np < 4; np++) {
                const uint32_t voff =
                    (uint32_t)((((np * 2 + (lane >> 4)) ^ vxor) << 4));
                uint32_t vh[4], vl[4];
                ldsm4t(vh, kvb + 2 * 8192 + rv + voff);
                ldsm4t(vl, kvb + 3 * 8192 + rv + voff);
                mma16816(o[2 * np + 0], ph[kb], vh + 0);
                mma16816(o[2 * np + 1], ph[kb], vh + 2);
                mma16816(o[2 * np + 0], ph[kb], vl + 0);
                mma16816(o[2 * np + 1], ph[kb], vl + 2);
                mma16816(o[2 * np + 0], pl[kb], vh + 0);
                mma16816(o[2 * np + 1], pl[kb], vh + 2);
            }
        }
        __syncthreads();   // all warps done with buffer before reuse
    }

    // ---- normalize + store out[b][t][d]
    const int b = bh >> 4, h = bh & 15;
    const float inv0 = 1.0f / l0;
    const float inv1 = 1.0f / l1;
    const int t0 = q0 + wm + (lane >> 2);
    #pragma unroll
    for (int j = 0; j < 8; j++) {
        const int d = h * 64 + j * 8 + (lane & 3) * 2;
        float2 v0 = { o[j][0] * inv0, o[j][1] * inv0 };
        float2 v1 = { o[j][2] * inv1, o[j][3] * inv1 };
        *(float2*)(out + ((size_t)b * TT + t0) * DD + d)       = v0;
        *(float2*)(out + ((size_t)b * TT + t0 + 8) * DD + d)   = v1;
    }
}

// ---------------------------------------------------------------------------
extern "C" void kernel_launch(void* const* d_in, const int* in_sizes, int n_in,
                              void* d_out, int out_size)
{
    const float* x  = (const float*)d_in[0];
    const float* Wq = (const float*)d_in[1];
    const float* bq = (const float*)d_in[2];
    const float* Wk = (const float*)d_in[3];
    const float* bk = (const float*)d_in[4];
    const float* Wv = (const float*)d_in[5];
    const float* bv = (const float*)d_in[6];
    float* out = (float*)d_out;

    static int attr_set = 0;
    if (!attr_set) {
        cudaFuncSetAttribute(qkv_mma_kernel,
                             cudaFuncAttributeMaxDynamicSharedMemorySize,
                             GEMM_SMEM);
        cudaFuncSetAttribute(attn_mma_kernel,
                             cudaFuncAttributeMaxDynamicSharedMemorySize,
                             ATT_SMEM);
        attr_set = 1;
    }

    convert_x_kernel<<<(BB * TT * DD) / 4 / 256, 256>>>(x);
    convert_w_kernel<<<dim3(DD / 32, DD / 32, 3), dim3(32, 8)>>>(Wq, Wk, Wv);

    qkv_mma_kernel<<<dim3(DD / 128, BB * TT / 128, 3), 256, GEMM_SMEM>>>(bq, bk, bv);

    attn_mma_kernel<<<dim3(TT / 128, BHH), 256, ATT_SMEM>>>(out);
}